// round 2
// baseline (speedup 1.0000x reference)
#include <cuda_runtime.h>

// Problem constants
#define NROWS 8192
#define DCOLS 1024

// Scratch (static __device__ arrays — allocation-free per harness rules)
__device__ float g_qkv[(size_t)6 * NROWS * DCOLS];     // 192 MB
__device__ float g_S[(size_t)NROWS * NROWS];           // 256 MB
__device__ float g_fused[(size_t)NROWS * 2 * DCOLS];   //  64 MB

// ---------------------------------------------------------------------------
// Generic fp32 GEMM: C[M,N] = A[M,K] @ op(B) (+ bias)
//   TRANS_B = false: B is [K, ldb] row-major
//   TRANS_B = true : B is [N, ldb] row-major (op(B)[k][n] = B[n][k])
// Tile: BM=BN=128, BK=16, 256 threads, 8x8 micro-tile, 2-stage smem pipeline.
// All dims are multiples of 128/16 here, no bounds checks needed.
// ---------------------------------------------------------------------------
template <bool TRANS_B, bool ADD_BIAS>
__global__ __launch_bounds__(256)
void gemm128(const float* __restrict__ A, int lda,
             const float* __restrict__ B, int ldb,
             float* __restrict__ C, int ldc,
             const float* __restrict__ bias, int K)
{
    __shared__ float As[2][16][128];   // As[s][k][m]  (A transposed in smem)
    __shared__ float Bs[2][16][128];   // Bs[s][k][n]

    const int tid = threadIdx.x;
    const int tx  = tid & 15;          // n micro-tile
    const int ty  = tid >> 4;          // m micro-tile
    const int m0  = blockIdx.y * 128;
    const int n0  = blockIdx.x * 128;

    // Per-thread global-load coordinates (2 float4 each for A and B)
    // A: slot f in [0,512): row=f>>2 (0..127), kq=(f&3)*4
    const int a_row0 = tid >> 2,        a_kq0 = (tid & 3) << 2;
    const int a_row1 = (tid + 256) >> 2, a_kq1 = ((tid + 256) & 3) << 2;
    // B (TRANS): n=f>>2, kq=(f&3)*4.   B (NOTRANS): k=f>>5, nq=(f&31)*4
    const int bt_n0 = a_row0, bt_kq0 = a_kq0;
    const int bt_n1 = a_row1, bt_kq1 = a_kq1;
    const int bn_k0 = tid >> 5,         bn_nq0 = (tid & 31) << 2;
    const int bn_k1 = (tid + 256) >> 5, bn_nq1 = ((tid + 256) & 31) << 2;

    float acc[8][8];
#pragma unroll
    for (int i = 0; i < 8; ++i)
#pragma unroll
        for (int j = 0; j < 8; ++j) acc[i][j] = 0.0f;

    // ---- helpers as lambdas ----
    auto loadA = [&](int kt, float4& va0, float4& va1) {
        va0 = *reinterpret_cast<const float4*>(&A[(size_t)(m0 + a_row0) * lda + kt + a_kq0]);
        va1 = *reinterpret_cast<const float4*>(&A[(size_t)(m0 + a_row1) * lda + kt + a_kq1]);
    };
    auto loadB = [&](int kt, float4& vb0, float4& vb1) {
        if (TRANS_B) {
            vb0 = *reinterpret_cast<const float4*>(&B[(size_t)(n0 + bt_n0) * ldb + kt + bt_kq0]);
            vb1 = *reinterpret_cast<const float4*>(&B[(size_t)(n0 + bt_n1) * ldb + kt + bt_kq1]);
        } else {
            vb0 = *reinterpret_cast<const float4*>(&B[(size_t)(kt + bn_k0) * ldb + n0 + bn_nq0]);
            vb1 = *reinterpret_cast<const float4*>(&B[(size_t)(kt + bn_k1) * ldb + n0 + bn_nq1]);
        }
    };
    auto storeA = [&](int s, const float4& va0, const float4& va1) {
        As[s][a_kq0 + 0][a_row0] = va0.x;  As[s][a_kq0 + 1][a_row0] = va0.y;
        As[s][a_kq0 + 2][a_row0] = va0.z;  As[s][a_kq0 + 3][a_row0] = va0.w;
        As[s][a_kq1 + 0][a_row1] = va1.x;  As[s][a_kq1 + 1][a_row1] = va1.y;
        As[s][a_kq1 + 2][a_row1] = va1.z;  As[s][a_kq1 + 3][a_row1] = va1.w;
    };
    auto storeB = [&](int s, const float4& vb0, const float4& vb1) {
        if (TRANS_B) {
            Bs[s][bt_kq0 + 0][bt_n0] = vb0.x;  Bs[s][bt_kq0 + 1][bt_n0] = vb0.y;
            Bs[s][bt_kq0 + 2][bt_n0] = vb0.z;  Bs[s][bt_kq0 + 3][bt_n0] = vb0.w;
            Bs[s][bt_kq1 + 0][bt_n1] = vb1.x;  Bs[s][bt_kq1 + 1][bt_n1] = vb1.y;
            Bs[s][bt_kq1 + 2][bt_n1] = vb1.z;  Bs[s][bt_kq1 + 3][bt_n1] = vb1.w;
        } else {
            *reinterpret_cast<float4*>(&Bs[s][bn_k0][bn_nq0]) = vb0;
            *reinterpret_cast<float4*>(&Bs[s][bn_k1][bn_nq1]) = vb1;
        }
    };

    // ---- prologue: stage 0 ----
    {
        float4 va0, va1, vb0, vb1;
        loadA(0, va0, va1);
        loadB(0, vb0, vb1);
        storeA(0, va0, va1);
        storeB(0, vb0, vb1);
    }
    __syncthreads();

    int s = 0;
    for (int kt = 0; kt < K; kt += 16) {
        // prefetch next tile into registers (overlaps with compute below)
        float4 va0, va1, vb0, vb1;
        const bool has_next = (kt + 16) < K;
        if (has_next) {
            loadA(kt + 16, va0, va1);
            loadB(kt + 16, vb0, vb1);
        }

        // compute current stage
#pragma unroll
        for (int k = 0; k < 16; ++k) {
            float a[8], b[8];
#pragma unroll
            for (int i = 0; i < 8; ++i) a[i] = As[s][k][ty * 8 + i];
#pragma unroll
            for (int j = 0; j < 8; ++j) b[j] = Bs[s][k][tx * 8 + j];
#pragma unroll
            for (int i = 0; i < 8; ++i)
#pragma unroll
                for (int j = 0; j < 8; ++j)
                    acc[i][j] = fmaf(a[i], b[j], acc[i][j]);
        }

        if (has_next) {
            storeA(s ^ 1, va0, va1);
            storeB(s ^ 1, vb0, vb1);
            __syncthreads();
            s ^= 1;
        }
    }

    // ---- epilogue ----
#pragma unroll
    for (int i = 0; i < 8; ++i) {
        float* crow = &C[(size_t)(m0 + ty * 8 + i) * ldc + n0 + tx * 8];
#pragma unroll
        for (int jq = 0; jq < 2; ++jq) {
            float4 v;
            v.x = acc[i][jq * 4 + 0];
            v.y = acc[i][jq * 4 + 1];
            v.z = acc[i][jq * 4 + 2];
            v.w = acc[i][jq * 4 + 3];
            if (ADD_BIAS) {
                const float* brow = &bias[n0 + tx * 8 + jq * 4];
                v.x += brow[0]; v.y += brow[1]; v.z += brow[2]; v.w += brow[3];
            }
            *reinterpret_cast<float4*>(&crow[jq * 4]) = v;
        }
    }
}

// ---------------------------------------------------------------------------
// In-place row softmax over S[8192,8192]. One block per row; whole row staged
// in 32 KB smem (single global read + single global write).
// ---------------------------------------------------------------------------
__global__ __launch_bounds__(256)
void softmax_row(float* __restrict__ S)
{
    __shared__ float row[NROWS];
    __shared__ float red[256];

    float* p = S + (size_t)blockIdx.x * NROWS;
    const int tid = threadIdx.x;

    float lmax = -3.0e38f;
    for (int i = tid * 4; i < NROWS; i += 1024) {
        float4 v = *reinterpret_cast<const float4*>(&p[i]);
        *reinterpret_cast<float4*>(&row[i]) = v;
        lmax = fmaxf(lmax, fmaxf(fmaxf(v.x, v.y), fmaxf(v.z, v.w)));
    }
    red[tid] = lmax;
    __syncthreads();
#pragma unroll
    for (int sft = 128; sft > 0; sft >>= 1) {
        if (tid < sft) red[tid] = fmaxf(red[tid], red[tid + sft]);
        __syncthreads();
    }
    const float bmax = red[0];
    __syncthreads();

    float lsum = 0.0f;
    for (int i = tid * 4; i < NROWS; i += 1024) {
        float4 v = *reinterpret_cast<float4*>(&row[i]);
        v.x = __expf(v.x - bmax);
        v.y = __expf(v.y - bmax);
        v.z = __expf(v.z - bmax);
        v.w = __expf(v.w - bmax);
        lsum += v.x + v.y + v.z + v.w;
        *reinterpret_cast<float4*>(&row[i]) = v;
    }
    red[tid] = lsum;
    __syncthreads();
#pragma unroll
    for (int sft = 128; sft > 0; sft >>= 1) {
        if (tid < sft) red[tid] += red[tid + sft];
        __syncthreads();
    }
    const float inv = 1.0f / red[0];
    __syncthreads();

    for (int i = tid * 4; i < NROWS; i += 1024) {
        float4 v = *reinterpret_cast<float4*>(&row[i]);
        v.x *= inv; v.y *= inv; v.z *= inv; v.w *= inv;
        *reinterpret_cast<float4*>(&p[i]) = v;
    }
}

// ---------------------------------------------------------------------------
// Launch sequence
// ---------------------------------------------------------------------------
extern "C" void kernel_launch(void* const* d_in, const int* in_sizes, int n_in,
                              void* d_out, int out_size)
{
    const float* img = (const float*)d_in[0];
    const float* tab = (const float*)d_in[1];
    const float* Wqi = (const float*)d_in[2];  const float* bqi = (const float*)d_in[3];
    const float* Wkt = (const float*)d_in[4];  const float* bkt = (const float*)d_in[5];
    const float* Wvt = (const float*)d_in[6];  const float* bvt = (const float*)d_in[7];
    const float* Wqt = (const float*)d_in[8];  const float* bqt = (const float*)d_in[9];
    const float* Wki = (const float*)d_in[10]; const float* bki = (const float*)d_in[11];
    const float* Wvi = (const float*)d_in[12]; const float* bvi = (const float*)d_in[13];
    const float* Wo  = (const float*)d_in[14]; const float* bo  = (const float*)d_in[15];
    float* out = (float*)d_out;

    float *qkv, *S, *fused;
    cudaGetSymbolAddress((void**)&qkv,   g_qkv);
    cudaGetSymbolAddress((void**)&S,     g_S);
    cudaGetSymbolAddress((void**)&fused, g_fused);

    const size_t ND = (size_t)NROWS * DCOLS;
    float* q1 = qkv + 0 * ND;   // q_img
    float* k1 = qkv + 1 * ND;   // k_tab
    float* v1 = qkv + 2 * ND;   // v_tab
    float* q2 = qkv + 3 * ND;   // q_tab
    float* k2 = qkv + 4 * ND;   // k_img
    float* v2 = qkv + 5 * ND;   // v_img

    dim3 blk(256);
    dim3 gProj(DCOLS / 128, NROWS / 128);        // (8, 64)
    dim3 gS(NROWS / 128, NROWS / 128);           // (64, 64)
    dim3 gOut(2 * DCOLS / 128, NROWS / 128);     // (16, 64)

    // Projections
    gemm128<false, true><<<gProj, blk>>>(img, DCOLS, Wqi, DCOLS, q1, DCOLS, bqi, DCOLS);
    gemm128<false, true><<<gProj, blk>>>(tab, DCOLS, Wkt, DCOLS, k1, DCOLS, bkt, DCOLS);
    gemm128<false, true><<<gProj, blk>>>(tab, DCOLS, Wvt, DCOLS, v1, DCOLS, bvt, DCOLS);
    gemm128<false, true><<<gProj, blk>>>(tab, DCOLS, Wqt, DCOLS, q2, DCOLS, bqt, DCOLS);
    gemm128<false, true><<<gProj, blk>>>(img, DCOLS, Wki, DCOLS, k2, DCOLS, bki, DCOLS);
    gemm128<false, true><<<gProj, blk>>>(img, DCOLS, Wvi, DCOLS, v2, DCOLS, bvi, DCOLS);

    // Branch 1: softmax(q_img @ k_tab^T) @ v_tab -> fused[:, 1024:2048]
    gemm128<true, false><<<gS, blk>>>(q1, DCOLS, k1, DCOLS, S, NROWS, nullptr, DCOLS);
    softmax_row<<<NROWS, 256>>>(S);
    gemm128<false, false><<<gProj, blk>>>(S, NROWS, v1, DCOLS, fused + DCOLS, 2 * DCOLS,
                                          nullptr, NROWS);

    // Branch 2: softmax(q_tab @ k_img^T) @ v_img -> fused[:, 0:1024]
    gemm128<true, false><<<gS, blk>>>(q2, DCOLS, k2, DCOLS, S, NROWS, nullptr, DCOLS);
    softmax_row<<<NROWS, 256>>>(S);
    gemm128<false, false><<<gProj, blk>>>(S, NROWS, v2, DCOLS, fused, 2 * DCOLS,
                                          nullptr, NROWS);

    // Output projection
    gemm128<false, true><<<gOut, blk>>>(fused, 2 * DCOLS, Wo, 2 * DCOLS, out, 2 * DCOLS,
                                        bo, 2 * DCOLS);
}

// round 4
// speedup vs baseline: 2.0637x; 2.0637x over previous
#include <cuda_runtime.h>
#include <cuda_fp16.h>
#include <cstdint>

#define NR 8192
#define DC 1024

// ---------------------------------------------------------------------------
// Static device scratch (allocation-free). All split-fp16 tensors are stored
// as [rows, 2K]: columns [0,K) = hi, [K,2K) = lo.
// ---------------------------------------------------------------------------
__device__ float  g_S[(size_t)NR * NR];                 // 256 MB logits
__device__ __half g_img2[(size_t)NR * 2 * DC];          // img  [8192,2048]
__device__ __half g_tab2[(size_t)NR * 2 * DC];          // tab  [8192,2048]
__device__ __half g_w2[(size_t)6 * DC * 2 * DC];        // 6x W^T [1024,2048]
__device__ __half g_wo2[(size_t)2 * DC * 4 * DC];       // Wo^T [2048,4096]
__device__ __half g_qk2[(size_t)4 * NR * 2 * DC];       // q1,k1,q2,k2 [8192,2048]
__device__ __half g_vt2[(size_t)2 * DC * 2 * NR];       // v1^T,v2^T [1024,16384]
__device__ __half g_S2[(size_t)NR * 2 * NR];            // probs [8192,16384] 268MB
__device__ __half g_fused2[(size_t)NR * 4 * DC];        // fused [8192,4096]

// ---------------------------------------------------------------------------
// helpers
// ---------------------------------------------------------------------------
__device__ __forceinline__ uint32_t smem_u32(const void* p) {
    uint32_t a;
    asm("{ .reg .u64 t; cvta.to.shared.u64 t, %1; cvt.u32.u64 %0, t; }" : "=r"(a) : "l"(p));
    return a;
}
__device__ __forceinline__ void cp16(uint32_t d, const void* g) {
    asm volatile("cp.async.cg.shared.global [%0], [%1], 16;"
                 :: "r"(d), "l"(__cvta_generic_to_global(g)) : "memory");
}
__device__ __forceinline__ uint32_t lds32(uint32_t a) {
    uint32_t v;
    asm volatile("ld.shared.u32 %0, [%1];" : "=r"(v) : "r"(a));
    return v;
}
__device__ __forceinline__ void mma16816(float* d, const uint32_t* a, const uint32_t* b) {
    asm("mma.sync.aligned.m16n8k16.row.col.f32.f16.f16.f32 "
        "{%0,%1,%2,%3}, {%4,%5,%6,%7}, {%8,%9}, {%0,%1,%2,%3};"
        : "+f"(d[0]), "+f"(d[1]), "+f"(d[2]), "+f"(d[3])
        : "r"(a[0]), "r"(a[1]), "r"(a[2]), "r"(a[3]), "r"(b[0]), "r"(b[1]));
}
__device__ __forceinline__ __half2 split_hi(float x0, float x1, __half2& lo) {
    __half h0 = __float2half_rn(x0), h1 = __float2half_rn(x1);
    lo = __halves2half2(__float2half_rn(x0 - __half2float(h0)),
                        __float2half_rn(x1 - __half2float(h1)));
    return __halves2half2(h0, h1);
}

// ---------------------------------------------------------------------------
// Split-fp16 NT GEMM:  C[M,N] = A[M,K] . B[N,K]^T  in 3 passes
//   (Ahi,Bhi), (Ahi,Blo), (Alo,Bhi); A,B stored [rows, 2K] fp16.
// Tile 128x128xBK32, 256 threads, cp.async 3-stage pipeline.
// OUT_MODE: 0 = fp32 to Cf, 1 = split fp16 to Ch (hi at col, lo at col+lo_off)
// BIAS: 0 none, 1 per-column, 2 per-row
// ---------------------------------------------------------------------------
#define TPB 256
#define AST 80                      // smem row stride bytes (64B data + 16B pad)
#define STG (128 * AST * 2)         // A+B tile bytes per stage = 20480
#define GSMEM (3 * STG)

template <int OUT_MODE, int BIAS>
__global__ __launch_bounds__(TPB)
void hgemm3(const __half* __restrict__ A, const __half* __restrict__ B, int K,
            float* __restrict__ Cf, __half* __restrict__ Ch,
            int ldc, int lo_off, const float* __restrict__ bias)
{
    extern __shared__ char smc[];
    const uint32_t sb = smem_u32(smc);
    const int tid = threadIdx.x;
    const int wid = tid >> 5, lane = tid & 31;
    const int g = lane >> 2, t = lane & 3;
    const int wm = wid & 1, wn = wid >> 1;          // warp 2x4 grid
    const int m0 = blockIdx.y * 128, n0 = blockIdx.x * 128;
    const size_t lda = 2 * (size_t)K;

    const int K32 = K >> 5;
    const int total = 3 * K32;

    const int lr = tid >> 2;                        // load row 0..63
    const int lk = (tid & 3) * 16;                  // load chunk byte 0..48

    auto load_stage = [&](int s, int step) {
        if (step < total) {
            const int seg = step / K32, kk = step - seg * K32;
            const size_t ak = (size_t)((seg == 2) ? K : 0) + kk * 32;
            const size_t bk = (size_t)((seg == 1) ? K : 0) + kk * 32;
            const __half* ga = A + (size_t)(m0 + lr) * lda + ak + (lk >> 1);
            const __half* gb = B + (size_t)(n0 + lr) * lda + bk + (lk >> 1);
            const uint32_t da = sb + s * STG + lr * AST + lk;
            const uint32_t db = da + 128 * AST;
            cp16(da, ga);
            cp16(db, gb);
            cp16(da + 64 * AST, ga + 64 * lda);
            cp16(db + 64 * AST, gb + 64 * lda);
        }
        asm volatile("cp.async.commit_group;" ::: "memory");
    };

    float acc[4][4][4];
#pragma unroll
    for (int i = 0; i < 4; ++i)
#pragma unroll
        for (int j = 0; j < 4; ++j)
#pragma unroll
            for (int r = 0; r < 4; ++r) acc[i][j][r] = 0.0f;

    load_stage(0, 0);
    load_stage(1, 1);

    for (int step = 0; step < total; ++step) {
        asm volatile("cp.async.wait_group 1;" ::: "memory");
        __syncthreads();
        load_stage((step + 2) % 3, step + 2);

        const uint32_t sa = sb + (step % 3) * STG + (wm * 64 + g) * AST + t * 4;
        const uint32_t sB = sb + (step % 3) * STG + 128 * AST + (wn * 32 + g) * AST + t * 4;

#pragma unroll
        for (int kh = 0; kh < 2; ++kh) {            // two k16 halves of BK=32
            const uint32_t ko = kh * 32;
            uint32_t af[4][4], bf[4][2];
#pragma unroll
            for (int mt = 0; mt < 4; ++mt) {
                const uint32_t base = sa + mt * 16 * AST + ko;
                af[mt][0] = lds32(base);
                af[mt][1] = lds32(base + 8 * AST);
                af[mt][2] = lds32(base + 16);
                af[mt][3] = lds32(base + 8 * AST + 16);
            }
#pragma unroll
            for (int nt = 0; nt < 4; ++nt) {
                const uint32_t base = sB + nt * 8 * AST + ko;
                bf[nt][0] = lds32(base);
                bf[nt][1] = lds32(base + 16);
            }
#pragma unroll
            for (int mt = 0; mt < 4; ++mt)
#pragma unroll
                for (int nt = 0; nt < 4; ++nt)
                    mma16816(acc[mt][nt], af[mt], bf[nt]);
        }
    }

    // ---- epilogue ----
#pragma unroll
    for (int mt = 0; mt < 4; ++mt) {
        const int r0 = m0 + wm * 64 + mt * 16 + g;
        const int r1 = r0 + 8;
#pragma unroll
        for (int nt = 0; nt < 4; ++nt) {
            const int col = n0 + wn * 32 + nt * 8 + 2 * t;
            float v00 = acc[mt][nt][0], v01 = acc[mt][nt][1];
            float v10 = acc[mt][nt][2], v11 = acc[mt][nt][3];
            if (BIAS == 1) {
                const float b0 = bias[col], b1 = bias[col + 1];
                v00 += b0; v01 += b1; v10 += b0; v11 += b1;
            } else if (BIAS == 2) {
                const float b0 = bias[r0], b1 = bias[r1];
                v00 += b0; v01 += b0; v10 += b1; v11 += b1;
            }
            if (OUT_MODE == 0) {
                *reinterpret_cast<float2*>(&Cf[(size_t)r0 * ldc + col]) = make_float2(v00, v01);
                *reinterpret_cast<float2*>(&Cf[(size_t)r1 * ldc + col]) = make_float2(v10, v11);
            } else {
                __half2 lo0, lo1;
                __half2 hi0 = split_hi(v00, v01, lo0);
                __half2 hi1 = split_hi(v10, v11, lo1);
                __half2* p0 = reinterpret_cast<__half2*>(&Ch[(size_t)r0 * ldc + col]);
                __half2* p1 = reinterpret_cast<__half2*>(&Ch[(size_t)r1 * ldc + col]);
                p0[0] = hi0;  p0[lo_off / 2] = lo0;
                p1[0] = hi1;  p1[lo_off / 2] = lo1;
            }
        }
    }
}

// ---------------------------------------------------------------------------
// fp32 [R,C] -> split fp16 [R,2C]
// ---------------------------------------------------------------------------
__global__ __launch_bounds__(256)
void convert_split(const float* __restrict__ in, __half* __restrict__ out,
                   int C, size_t total)
{
    size_t i = ((size_t)blockIdx.x * 256 + threadIdx.x) * 4;
    if (i >= total) return;
    float4 v = *reinterpret_cast<const float4*>(&in[i]);
    size_t r = i / C;
    int c = (int)(i - r * C);
    __half2 lo0, lo1;
    __half2 hi0 = split_hi(v.x, v.y, lo0);
    __half2 hi1 = split_hi(v.z, v.w, lo1);
    __half* row = out + r * (2 * (size_t)C);
    *reinterpret_cast<__half2*>(&row[c])         = hi0;
    *reinterpret_cast<__half2*>(&row[c + 2])     = hi1;
    *reinterpret_cast<__half2*>(&row[C + c])     = lo0;
    *reinterpret_cast<__half2*>(&row[C + c + 2]) = lo1;
}

// ---------------------------------------------------------------------------
// fp32 [R,C] -> transposed split fp16 [C,2R]
// ---------------------------------------------------------------------------
__global__ __launch_bounds__(256)
void transpose_split(const float* __restrict__ in, __half* __restrict__ out,
                     int R, int C)
{
    __shared__ float tl[32][33];
    const int bx = blockIdx.x * 32, by = blockIdx.y * 32;
    const int tx = threadIdx.x, ty = threadIdx.y;
#pragma unroll
    for (int j = ty; j < 32; j += 8)
        tl[j][tx] = in[(size_t)(by + j) * C + bx + tx];
    __syncthreads();
#pragma unroll
    for (int j = ty; j < 32; j += 8) {
        const float v = tl[tx][j];
        const __half h = __float2half_rn(v);
        const __half l = __float2half_rn(v - __half2float(h));
        __half* row = out + (size_t)(bx + j) * (2 * (size_t)R);
        row[by + tx]     = h;
        row[R + by + tx] = l;
    }
}

// ---------------------------------------------------------------------------
// Row softmax: read fp32 logits S[8192,8192], write split fp16 probs S2
// ---------------------------------------------------------------------------
__global__ __launch_bounds__(256)
void softmax_split(const float* __restrict__ S, __half* __restrict__ S2)
{
    __shared__ float row[NR];
    __shared__ float red[256];
    const float* p = S + (size_t)blockIdx.x * NR;
    __half* o = S2 + (size_t)blockIdx.x * (2 * (size_t)NR);
    const int tid = threadIdx.x;

    float lmax = -3.0e38f;
    for (int i = tid * 4; i < NR; i += 1024) {
        float4 v = *reinterpret_cast<const float4*>(&p[i]);
        *reinterpret_cast<float4*>(&row[i]) = v;
        lmax = fmaxf(lmax, fmaxf(fmaxf(v.x, v.y), fmaxf(v.z, v.w)));
    }
    red[tid] = lmax;
    __syncthreads();
#pragma unroll
    for (int s = 128; s > 0; s >>= 1) {
        if (tid < s) red[tid] = fmaxf(red[tid], red[tid + s]);
        __syncthreads();
    }
    const float bmax = red[0];
    __syncthreads();

    float lsum = 0.0f;
    for (int i = tid * 4; i < NR; i += 1024) {
        float4 v = *reinterpret_cast<float4*>(&row[i]);
        v.x = __expf(v.x - bmax); v.y = __expf(v.y - bmax);
        v.z = __expf(v.z - bmax); v.w = __expf(v.w - bmax);
        lsum += v.x + v.y + v.z + v.w;
        *reinterpret_cast<float4*>(&row[i]) = v;
    }
    red[tid] = lsum;
    __syncthreads();
#pragma unroll
    for (int s = 128; s > 0; s >>= 1) {
        if (tid < s) red[tid] += red[tid + s];
        __syncthreads();
    }
    const float inv = 1.0f / red[0];
    __syncthreads();

    for (int i = tid * 4; i < NR; i += 1024) {
        float4 v = *reinterpret_cast<float4*>(&row[i]);
        v.x *= inv; v.y *= inv; v.z *= inv; v.w *= inv;
        __half2 lo0, lo1;
        __half2 hi0 = split_hi(v.x, v.y, lo0);
        __half2 hi1 = split_hi(v.z, v.w, lo1);
        *reinterpret_cast<__half2*>(&o[i])          = hi0;
        *reinterpret_cast<__half2*>(&o[i + 2])      = hi1;
        *reinterpret_cast<__half2*>(&o[NR + i])     = lo0;
        *reinterpret_cast<__half2*>(&o[NR + i + 2]) = lo1;
    }
}

// ---------------------------------------------------------------------------
// Launch sequence
// ---------------------------------------------------------------------------
extern "C" void kernel_launch(void* const* d_in, const int* in_sizes, int n_in,
                              void* d_out, int out_size)
{
    const float* img = (const float*)d_in[0];
    const float* tab = (const float*)d_in[1];
    const float* Wqi = (const float*)d_in[2];  const float* bqi = (const float*)d_in[3];
    const float* Wkt = (const float*)d_in[4];  const float* bkt = (const float*)d_in[5];
    const float* Wvt = (const float*)d_in[6];  const float* bvt = (const float*)d_in[7];
    const float* Wqt = (const float*)d_in[8];  const float* bqt = (const float*)d_in[9];
    const float* Wki = (const float*)d_in[10]; const float* bki = (const float*)d_in[11];
    const float* Wvi = (const float*)d_in[12]; const float* bvi = (const float*)d_in[13];
    const float* Wo  = (const float*)d_in[14]; const float* bo  = (const float*)d_in[15];
    float* out = (float*)d_out;

    cudaFuncSetAttribute(hgemm3<0,0>, cudaFuncAttributeMaxDynamicSharedMemorySize, GSMEM);
    cudaFuncSetAttribute(hgemm3<0,1>, cudaFuncAttributeMaxDynamicSharedMemorySize, GSMEM);
    cudaFuncSetAttribute(hgemm3<1,0>, cudaFuncAttributeMaxDynamicSharedMemorySize, GSMEM);
    cudaFuncSetAttribute(hgemm3<1,1>, cudaFuncAttributeMaxDynamicSharedMemorySize, GSMEM);
    cudaFuncSetAttribute(hgemm3<1,2>, cudaFuncAttributeMaxDynamicSharedMemorySize, GSMEM);

    float *S;
    __half *img2, *tab2, *w2, *wo2, *qk2, *vt2, *S2, *fused2;
    cudaGetSymbolAddress((void**)&S,      g_S);
    cudaGetSymbolAddress((void**)&img2,   g_img2);
    cudaGetSymbolAddress((void**)&tab2,   g_tab2);
    cudaGetSymbolAddress((void**)&w2,     g_w2);
    cudaGetSymbolAddress((void**)&wo2,    g_wo2);
    cudaGetSymbolAddress((void**)&qk2,    g_qk2);
    cudaGetSymbolAddress((void**)&vt2,    g_vt2);
    cudaGetSymbolAddress((void**)&S2,     g_S2);
    cudaGetSymbolAddress((void**)&fused2, g_fused2);

    const size_t W2SZ = (size_t)DC * 2 * DC;          // per weight^T
    __half* wqi2 = w2 + 0 * W2SZ;  __half* wkt2 = w2 + 1 * W2SZ;
    __half* wvt2 = w2 + 2 * W2SZ;  __half* wqt2 = w2 + 3 * W2SZ;
    __half* wki2 = w2 + 4 * W2SZ;  __half* wvi2 = w2 + 5 * W2SZ;
    const size_t QK2 = (size_t)NR * 2 * DC;
    __half* q12 = qk2 + 0 * QK2;   __half* k12 = qk2 + 1 * QK2;
    __half* q22 = qk2 + 2 * QK2;   __half* k22 = qk2 + 3 * QK2;
    __half* v1t2 = vt2;            __half* v2t2 = vt2 + (size_t)DC * 2 * NR;

    // ---- input conversions ----
    const size_t tot = (size_t)NR * DC;
    convert_split<<<(unsigned)((tot / 4 + 255) / 256), 256>>>(img, img2, DC, tot);
    convert_split<<<(unsigned)((tot / 4 + 255) / 256), 256>>>(tab, tab2, DC, tot);
    dim3 tb(32, 8);
    dim3 gw(DC / 32, DC / 32);
    transpose_split<<<gw, tb>>>(Wqi, wqi2, DC, DC);
    transpose_split<<<gw, tb>>>(Wkt, wkt2, DC, DC);
    transpose_split<<<gw, tb>>>(Wvt, wvt2, DC, DC);
    transpose_split<<<gw, tb>>>(Wqt, wqt2, DC, DC);
    transpose_split<<<gw, tb>>>(Wki, wki2, DC, DC);
    transpose_split<<<gw, tb>>>(Wvi, wvi2, DC, DC);
    dim3 gwo(2 * DC / 32, 2 * DC / 32);
    transpose_split<<<gwo, tb>>>(Wo, wo2, 2 * DC, 2 * DC);

    // ---- projections (split fp16 out) ----
    dim3 gP(DC / 128, NR / 128);        // (8, 64)
    hgemm3<1,1><<<gP, TPB, GSMEM>>>(img2, wqi2, DC, nullptr, q12, 2 * DC, DC, bqi);
    hgemm3<1,1><<<gP, TPB, GSMEM>>>(tab2, wkt2, DC, nullptr, k12, 2 * DC, DC, bkt);
    hgemm3<1,1><<<gP, TPB, GSMEM>>>(tab2, wqt2, DC, nullptr, q22, 2 * DC, DC, bqt);
    hgemm3<1,1><<<gP, TPB, GSMEM>>>(img2, wki2, DC, nullptr, k22, 2 * DC, DC, bki);
    // v^T computed directly transposed: v1^T = Wvt^T . tab^T (+bvt per-row)
    dim3 gV(NR / 128, DC / 128);        // (64, 8)
    hgemm3<1,2><<<gV, TPB, GSMEM>>>(wvt2, tab2, DC, nullptr, v1t2, 2 * NR, NR, bvt);
    hgemm3<1,2><<<gV, TPB, GSMEM>>>(wvi2, img2, DC, nullptr, v2t2, 2 * NR, NR, bvi);

    dim3 gS(NR / 128, NR / 128);        // (64, 64)
    dim3 gPV(DC / 128, NR / 128);       // (8, 64)

    // ---- branch 1: attended_tabular -> fused cols [1024,2048) ----
    hgemm3<0,0><<<gS, TPB, GSMEM>>>(q12, k12, DC, S, nullptr, NR, 0, nullptr);
    softmax_split<<<NR, 256>>>(S, S2);
    hgemm3<1,0><<<gPV, TPB, GSMEM>>>(S2, v1t2, NR, nullptr, fused2 + DC, 4 * DC, 2 * DC, nullptr);

    // ---- branch 2: attended_image -> fused cols [0,1024) ----
    hgemm3<0,0><<<gS, TPB, GSMEM>>>(q22, k22, DC, S, nullptr, NR, 0, nullptr);
    softmax_split<<<NR, 256>>>(S, S2);
    hgemm3<1,0><<<gPV, TPB, GSMEM>>>(S2, v2t2, NR, nullptr, fused2, 4 * DC, 2 * DC, nullptr);

    // ---- output projection (fp32 out) ----
    dim3 gO(2 * DC / 128, NR / 128);    // (16, 64)
    hgemm3<0,1><<<gO, TPB, GSMEM>>>(fused2, wo2, 2 * DC, out, nullptr, 2 * DC, 0, bo);
}

// round 5
// speedup vs baseline: 2.4843x; 1.2038x over previous
#include <cuda_runtime.h>
#include <cuda_fp16.h>
#include <cstdint>

#define NR 8192
#define DC 1024

// ---------------------------------------------------------------------------
// Static device scratch. Split-fp16 tensors stored [rows, 2K]: hi | lo.
// ---------------------------------------------------------------------------
__device__ float  g_S[(size_t)NR * NR];                 // 256 MB logits
__device__ __half g_img2[(size_t)NR * 2 * DC];
__device__ __half g_tab2[(size_t)NR * 2 * DC];
__device__ __half g_w2[(size_t)6 * DC * 2 * DC];        // 6x W^T [1024,2048]
__device__ __half g_wo2[(size_t)2 * DC * 4 * DC];       // Wo^T [2048,4096]
__device__ __half g_qk2[(size_t)4 * NR * 2 * DC];       // q1,k1,q2,k2
__device__ __half g_vt2[(size_t)2 * DC * 2 * NR];       // v1^T,v2^T [1024,16384]
__device__ __half g_S2[(size_t)NR * NR];                // probs hi-only [8192,8192]
__device__ __half g_fused2[(size_t)NR * 4 * DC];        // fused split [8192,4096]

// ---------------------------------------------------------------------------
// helpers
// ---------------------------------------------------------------------------
__device__ __forceinline__ uint32_t smem_u32(const void* p) {
    uint32_t a;
    asm("{ .reg .u64 t; cvta.to.shared.u64 t, %1; cvt.u32.u64 %0, t; }" : "=r"(a) : "l"(p));
    return a;
}
__device__ __forceinline__ void cp16(uint32_t d, const void* g) {
    asm volatile("cp.async.cg.shared.global [%0], [%1], 16;"
                 :: "r"(d), "l"(__cvta_generic_to_global(g)) : "memory");
}
__device__ __forceinline__ void ldm4(uint32_t* r, uint32_t a) {
    asm volatile("ldmatrix.sync.aligned.m8n8.x4.shared.b16 {%0,%1,%2,%3}, [%4];"
                 : "=r"(r[0]), "=r"(r[1]), "=r"(r[2]), "=r"(r[3]) : "r"(a));
}
__device__ __forceinline__ void mma16816(float* d, const uint32_t* a, const uint32_t* b) {
    asm("mma.sync.aligned.m16n8k16.row.col.f32.f16.f16.f32 "
        "{%0,%1,%2,%3}, {%4,%5,%6,%7}, {%8,%9}, {%0,%1,%2,%3};"
        : "+f"(d[0]), "+f"(d[1]), "+f"(d[2]), "+f"(d[3])
        : "r"(a[0]), "r"(a[1]), "r"(a[2]), "r"(a[3]), "r"(b[0]), "r"(b[1]));
}
__device__ __forceinline__ __half2 split_hi(float x0, float x1, __half2& lo) {
    __half h0 = __float2half_rn(x0), h1 = __float2half_rn(x1);
    lo = __halves2half2(__float2half_rn(x0 - __half2float(h0)),
                        __float2half_rn(x1 - __half2float(h1)));
    return __halves2half2(h0, h1);
}

// ---------------------------------------------------------------------------
// Split-fp16 NT GEMM:  C[M,N] = A[M,K] . B[N,K]^T
// PASSES=3: (Ahi,Bhi)+(Ahi,Blo)+(Alo,Bhi).  PASSES=2: first two (A lo unused).
// Tile 128x128xBK32, 256 threads, cp.async 3-stage, ldmatrix fragment loads.
// OUT_MODE: 0 = fp32 to Cf, 1 = split fp16 to Ch (hi at col, lo at col+lo_off)
// BIAS: 0 none, 1 per-column, 2 per-row
// ---------------------------------------------------------------------------
#define TPB 256
#define AST 80
#define STG (128 * AST * 2)
#define GSMEM (3 * STG)

template <int OUT_MODE, int BIAS, int PASSES>
__global__ __launch_bounds__(TPB)
void hgemm3(const __half* __restrict__ A, const __half* __restrict__ B, int K,
            size_t ldA, size_t ldB,
            float* __restrict__ Cf, __half* __restrict__ Ch,
            int ldc, int lo_off, const float* __restrict__ bias)
{
    extern __shared__ char smc[];
    const uint32_t sb = smem_u32(smc);
    const int tid = threadIdx.x;
    const int wid = tid >> 5, lane = tid & 31;
    const int g = lane >> 2, t = lane & 3;
    const int wm = wid & 1, wn = wid >> 1;
    const int m0 = blockIdx.y * 128, n0 = blockIdx.x * 128;

    const int K32 = K >> 5;
    const int total = PASSES * K32;

    const int lr = tid >> 2;
    const int lk = (tid & 3) * 16;

    auto load_stage = [&](int s, int step) {
        if (step < total) {
            const int seg = step / K32, kk = step - seg * K32;
            const size_t ak = (size_t)((seg == 2) ? K : 0) + kk * 32;
            const size_t bk = (size_t)((seg == 1) ? K : 0) + kk * 32;
            const __half* ga = A + (size_t)(m0 + lr) * ldA + ak + (lk >> 1);
            const __half* gb = B + (size_t)(n0 + lr) * ldB + bk + (lk >> 1);
            const uint32_t da = sb + s * STG + lr * AST + lk;
            const uint32_t db = da + 128 * AST;
            cp16(da, ga);
            cp16(db, gb);
            cp16(da + 64 * AST, ga + 64 * ldA);
            cp16(db + 64 * AST, gb + 64 * ldB);
        }
        asm volatile("cp.async.commit_group;" ::: "memory");
    };

    float acc[4][4][4];
#pragma unroll
    for (int i = 0; i < 4; ++i)
#pragma unroll
        for (int j = 0; j < 4; ++j)
#pragma unroll
            for (int r = 0; r < 4; ++r) acc[i][j][r] = 0.0f;

    // ldmatrix per-lane address offsets (within a stage)
    // A: matrices m0..m3 = (rows0-7,ko) (rows8-15,ko) (rows0-7,ko+16) (rows8-15,ko+16)
    const uint32_t aoff = (uint32_t)(wm * 64 + (lane & 15)) * AST + ((lane >> 4) << 4);
    // B: m0..m3 = (n0-7,ko) (n0-7,ko+16) (n8-15,ko) (n8-15,ko+16)
    const uint32_t boff = 128 * AST +
        (uint32_t)(wn * 32 + ((lane & 7) | ((lane >> 1) & 8))) * AST +
        (((lane >> 3) & 1) << 4);

    load_stage(0, 0);
    load_stage(1, 1);

    for (int step = 0; step < total; ++step) {
        asm volatile("cp.async.wait_group 1;" ::: "memory");
        __syncthreads();
        load_stage((step + 2) % 3, step + 2);

        const uint32_t sbase = sb + (step % 3) * STG;

#pragma unroll
        for (int kh = 0; kh < 2; ++kh) {
            const uint32_t ko = kh * 32;
            uint32_t af[4][4], bf[4][2];
#pragma unroll
            for (int mt = 0; mt < 4; ++mt)
                ldm4(af[mt], sbase + aoff + (uint32_t)mt * 16 * AST + ko);
#pragma unroll
            for (int np = 0; np < 2; ++np) {
                uint32_t r[4];
                ldm4(r, sbase + boff + (uint32_t)np * 16 * AST + ko);
                bf[np * 2][0] = r[0];  bf[np * 2][1] = r[1];
                bf[np * 2 + 1][0] = r[2];  bf[np * 2 + 1][1] = r[3];
            }
#pragma unroll
            for (int mt = 0; mt < 4; ++mt)
#pragma unroll
                for (int nt = 0; nt < 4; ++nt)
                    mma16816(acc[mt][nt], af[mt], bf[nt]);
        }
    }

    // ---- epilogue ----
#pragma unroll
    for (int mt = 0; mt < 4; ++mt) {
        const int r0 = m0 + wm * 64 + mt * 16 + g;
        const int r1 = r0 + 8;
#pragma unroll
        for (int nt = 0; nt < 4; ++nt) {
            const int col = n0 + wn * 32 + nt * 8 + 2 * t;
            float v00 = acc[mt][nt][0], v01 = acc[mt][nt][1];
            float v10 = acc[mt][nt][2], v11 = acc[mt][nt][3];
            if (BIAS == 1) {
                const float b0 = bias[col], b1 = bias[col + 1];
                v00 += b0; v01 += b1; v10 += b0; v11 += b1;
            } else if (BIAS == 2) {
                const float b0 = bias[r0], b1 = bias[r1];
                v00 += b0; v01 += b0; v10 += b1; v11 += b1;
            }
            if (OUT_MODE == 0) {
                *reinterpret_cast<float2*>(&Cf[(size_t)r0 * ldc + col]) = make_float2(v00, v01);
                *reinterpret_cast<float2*>(&Cf[(size_t)r1 * ldc + col]) = make_float2(v10, v11);
            } else {
                __half2 lo0, lo1;
                __half2 hi0 = split_hi(v00, v01, lo0);
                __half2 hi1 = split_hi(v10, v11, lo1);
                __half2* p0 = reinterpret_cast<__half2*>(&Ch[(size_t)r0 * ldc + col]);
                __half2* p1 = reinterpret_cast<__half2*>(&Ch[(size_t)r1 * ldc + col]);
                p0[0] = hi0;  p0[lo_off / 2] = lo0;
                p1[0] = hi1;  p1[lo_off / 2] = lo1;
            }
        }
    }
}

// ---------------------------------------------------------------------------
// fp32 [R,C] -> split fp16 [R,2C]
// ---------------------------------------------------------------------------
__global__ __launch_bounds__(256)
void convert_split(const float* __restrict__ in, __half* __restrict__ out,
                   int C, size_t total)
{
    size_t i = ((size_t)blockIdx.x * 256 + threadIdx.x) * 4;
    if (i >= total) return;
    float4 v = *reinterpret_cast<const float4*>(&in[i]);
    size_t r = i / C;
    int c = (int)(i - r * C);
    __half2 lo0, lo1;
    __half2 hi0 = split_hi(v.x, v.y, lo0);
    __half2 hi1 = split_hi(v.z, v.w, lo1);
    __half* row = out + r * (2 * (size_t)C);
    *reinterpret_cast<__half2*>(&row[c])         = hi0;
    *reinterpret_cast<__half2*>(&row[c + 2])     = hi1;
    *reinterpret_cast<__half2*>(&row[C + c])     = lo0;
    *reinterpret_cast<__half2*>(&row[C + c + 2]) = lo1;
}

// ---------------------------------------------------------------------------
// fp32 [R,C] -> transposed split fp16 [C,2R]
// ---------------------------------------------------------------------------
__global__ __launch_bounds__(256)
void transpose_split(const float* __restrict__ in, __half* __restrict__ out,
                     int R, int C)
{
    __shared__ float tl[32][33];
    const int bx = blockIdx.x * 32, by = blockIdx.y * 32;
    const int tx = threadIdx.x, ty = threadIdx.y;
#pragma unroll
    for (int j = ty; j < 32; j += 8)
        tl[j][tx] = in[(size_t)(by + j) * C + bx + tx];
    __syncthreads();
#pragma unroll
    for (int j = ty; j < 32; j += 8) {
        const float v = tl[tx][j];
        const __half h = __float2half_rn(v);
        const __half l = __float2half_rn(v - __half2float(h));
        __half* row = out + (size_t)(bx + j) * (2 * (size_t)R);
        row[by + tx]     = h;
        row[R + by + tx] = l;
    }
}

// ---------------------------------------------------------------------------
// Row softmax: fp32 logits -> fp16 probs (hi only, compact [NR,NR])
// ---------------------------------------------------------------------------
__global__ __launch_bounds__(256)
void softmax_hi(const float* __restrict__ S, __half* __restrict__ S2)
{
    __shared__ float row[NR];
    __shared__ float red[256];
    const float* p = S + (size_t)blockIdx.x * NR;
    __half* o = S2 + (size_t)blockIdx.x * NR;
    const int tid = threadIdx.x;

    float lmax = -3.0e38f;
    for (int i = tid * 4; i < NR; i += 1024) {
        float4 v = *reinterpret_cast<const float4*>(&p[i]);
        *reinterpret_cast<float4*>(&row[i]) = v;
        lmax = fmaxf(lmax, fmaxf(fmaxf(v.x, v.y), fmaxf(v.z, v.w)));
    }
    red[tid] = lmax;
    __syncthreads();
#pragma unroll
    for (int s = 128; s > 0; s >>= 1) {
        if (tid < s) red[tid] = fmaxf(red[tid], red[tid + s]);
        __syncthreads();
    }
    const float bmax = red[0];
    __syncthreads();

    float lsum = 0.0f;
    for (int i = tid * 4; i < NR; i += 1024) {
        float4 v = *reinterpret_cast<float4*>(&row[i]);
        v.x = __expf(v.x - bmax); v.y = __expf(v.y - bmax);
        v.z = __expf(v.z - bmax); v.w = __expf(v.w - bmax);
        lsum += v.x + v.y + v.z + v.w;
        *reinterpret_cast<float4*>(&row[i]) = v;
    }
    red[tid] = lsum;
    __syncthreads();
#pragma unroll
    for (int s = 128; s > 0; s >>= 1) {
        if (tid < s) red[tid] += red[tid + s];
        __syncthreads();
    }
    const float inv = 1.0f / red[0];
    __syncthreads();

    for (int i = tid * 4; i < NR; i += 1024) {
        float4 v = *reinterpret_cast<float4*>(&row[i]);
        *reinterpret_cast<__half2*>(&o[i]) =
            __halves2half2(__float2half_rn(v.x * inv), __float2half_rn(v.y * inv));
        *reinterpret_cast<__half2*>(&o[i + 2]) =
            __halves2half2(__float2half_rn(v.z * inv), __float2half_rn(v.w * inv));
    }
}

// ---------------------------------------------------------------------------
// Launch sequence
// ---------------------------------------------------------------------------
extern "C" void kernel_launch(void* const* d_in, const int* in_sizes, int n_in,
                              void* d_out, int out_size)
{
    const float* img = (const float*)d_in[0];
    const float* tab = (const float*)d_in[1];
    const float* Wqi = (const float*)d_in[2];  const float* bqi = (const float*)d_in[3];
    const float* Wkt = (const float*)d_in[4];  const float* bkt = (const float*)d_in[5];
    const float* Wvt = (const float*)d_in[6];  const float* bvt = (const float*)d_in[7];
    const float* Wqt = (const float*)d_in[8];  const float* bqt = (const float*)d_in[9];
    const float* Wki = (const float*)d_in[10]; const float* bki = (const float*)d_in[11];
    const float* Wvi = (const float*)d_in[12]; const float* bvi = (const float*)d_in[13];
    const float* Wo  = (const float*)d_in[14]; const float* bo  = (const float*)d_in[15];
    float* out = (float*)d_out;

    cudaFuncSetAttribute(hgemm3<0,0,3>, cudaFuncAttributeMaxDynamicSharedMemorySize, GSMEM);
    cudaFuncSetAttribute(hgemm3<0,1,3>, cudaFuncAttributeMaxDynamicSharedMemorySize, GSMEM);
    cudaFuncSetAttribute(hgemm3<1,0,2>, cudaFuncAttributeMaxDynamicSharedMemorySize, GSMEM);
    cudaFuncSetAttribute(hgemm3<1,1,3>, cudaFuncAttributeMaxDynamicSharedMemorySize, GSMEM);
    cudaFuncSetAttribute(hgemm3<1,2,3>, cudaFuncAttributeMaxDynamicSharedMemorySize, GSMEM);

    float *S;
    __half *img2, *tab2, *w2, *wo2, *qk2, *vt2, *S2, *fused2;
    cudaGetSymbolAddress((void**)&S,      g_S);
    cudaGetSymbolAddress((void**)&img2,   g_img2);
    cudaGetSymbolAddress((void**)&tab2,   g_tab2);
    cudaGetSymbolAddress((void**)&w2,     g_w2);
    cudaGetSymbolAddress((void**)&wo2,    g_wo2);
    cudaGetSymbolAddress((void**)&qk2,    g_qk2);
    cudaGetSymbolAddress((void**)&vt2,    g_vt2);
    cudaGetSymbolAddress((void**)&S2,     g_S2);
    cudaGetSymbolAddress((void**)&fused2, g_fused2);

    const size_t W2SZ = (size_t)DC * 2 * DC;
    __half* wqi2 = w2 + 0 * W2SZ;  __half* wkt2 = w2 + 1 * W2SZ;
    __half* wvt2 = w2 + 2 * W2SZ;  __half* wqt2 = w2 + 3 * W2SZ;
    __half* wki2 = w2 + 4 * W2SZ;  __half* wvi2 = w2 + 5 * W2SZ;
    const size_t QK2 = (size_t)NR * 2 * DC;
    __half* q12 = qk2 + 0 * QK2;   __half* k12 = qk2 + 1 * QK2;
    __half* q22 = qk2 + 2 * QK2;   __half* k22 = qk2 + 3 * QK2;
    __half* v1t2 = vt2;            __half* v2t2 = vt2 + (size_t)DC * 2 * NR;

    // ---- input conversions ----
    const size_t tot = (size_t)NR * DC;
    convert_split<<<(unsigned)((tot / 4 + 255) / 256), 256>>>(img, img2, DC, tot);
    convert_split<<<(unsigned)((tot / 4 + 255) / 256), 256>>>(tab, tab2, DC, tot);
    dim3 tb(32, 8);
    dim3 gw(DC / 32, DC / 32);
    transpose_split<<<gw, tb>>>(Wqi, wqi2, DC, DC);
    transpose_split<<<gw, tb>>>(Wkt, wkt2, DC, DC);
    transpose_split<<<gw, tb>>>(Wvt, wvt2, DC, DC);
    transpose_split<<<gw, tb>>>(Wqt, wqt2, DC, DC);
    transpose_split<<<gw, tb>>>(Wki, wki2, DC, DC);
    transpose_split<<<gw, tb>>>(Wvi, wvi2, DC, DC);
    dim3 gwo(2 * DC / 32, 2 * DC / 32);
    transpose_split<<<gwo, tb>>>(Wo, wo2, 2 * DC, 2 * DC);

    // ---- projections (split fp16 out, 3-pass) ----
    dim3 gP(DC / 128, NR / 128);
    hgemm3<1,1,3><<<gP, TPB, GSMEM>>>(img2, wqi2, DC, 2*DC, 2*DC, nullptr, q12, 2*DC, DC, bqi);
    hgemm3<1,1,3><<<gP, TPB, GSMEM>>>(tab2, wkt2, DC, 2*DC, 2*DC, nullptr, k12, 2*DC, DC, bkt);
    hgemm3<1,1,3><<<gP, TPB, GSMEM>>>(tab2, wqt2, DC, 2*DC, 2*DC, nullptr, q22, 2*DC, DC, bqt);
    hgemm3<1,1,3><<<gP, TPB, GSMEM>>>(img2, wki2, DC, 2*DC, 2*DC, nullptr, k22, 2*DC, DC, bki);
    // v^T computed directly transposed: v1^T = Wvt^T . tab^T (+bvt per-row)
    dim3 gV(NR / 128, DC / 128);
    hgemm3<1,2,3><<<gV, TPB, GSMEM>>>(wvt2, tab2, DC, 2*DC, 2*DC, nullptr, v1t2, 2*NR, NR, bvt);
    hgemm3<1,2,3><<<gV, TPB, GSMEM>>>(wvi2, img2, DC, 2*DC, 2*DC, nullptr, v2t2, 2*NR, NR, bvi);

    dim3 gS(NR / 128, NR / 128);
    dim3 gPV(DC / 128, NR / 128);

    // ---- branch 1: attended_tabular -> fused cols [1024,2048) ----
    hgemm3<0,0,3><<<gS, TPB, GSMEM>>>(q12, k12, DC, 2*DC, 2*DC, S, nullptr, NR, 0, nullptr);
    softmax_hi<<<NR, 256>>>(S, S2);
    hgemm3<1,0,2><<<gPV, TPB, GSMEM>>>(S2, v1t2, NR, NR, 2*NR, nullptr, fused2 + DC, 4*DC, 2*DC, nullptr);

    // ---- branch 2: attended_image -> fused cols [0,1024) ----
    hgemm3<0,0,3><<<gS, TPB, GSMEM>>>(q22, k22, DC, 2*DC, 2*DC, S, nullptr, NR, 0, nullptr);
    softmax_hi<<<NR, 256>>>(S, S2);
    hgemm3<1,0,2><<<gPV, TPB, GSMEM>>>(S2, v2t2, NR, NR, 2*NR, nullptr, fused2, 4*DC, 2*DC, nullptr);

    // ---- output projection (fp32 out, 3-pass) ----
    dim3 gO(2 * DC / 128, NR / 128);
    hgemm3<0,1,3><<<gO, TPB, GSMEM>>>(fused2, wo2, 2*DC, 4*DC, 4*DC, out, nullptr, 2*DC, 0, bo);
}

// round 6
// speedup vs baseline: 3.3084x; 1.3317x over previous
#include <cuda_runtime.h>
#include <cuda_fp16.h>
#include <cstdint>

#define NR 8192
#define DC 1024

// ---------------------------------------------------------------------------
// Static device scratch. Split-fp16 tensors stored [rows, 2K]: hi | lo.
// ---------------------------------------------------------------------------
__device__ float  g_S[(size_t)NR * NR];                 // 256 MB logits
__device__ __half g_img2[(size_t)NR * 2 * DC];
__device__ __half g_tab2[(size_t)NR * 2 * DC];
__device__ __half g_w2[(size_t)6 * DC * 2 * DC];        // 6x W^T [1024,2048]
__device__ __half g_wo2[(size_t)2 * DC * 4 * DC];       // Wo^T [2048,4096]
__device__ __half g_qk2[(size_t)4 * NR * 2 * DC];       // q1,k1,q2,k2
__device__ __half g_vt2[(size_t)2 * DC * 2 * NR];       // v1^T,v2^T [1024,16384]
__device__ __half g_S2[(size_t)NR * NR];                // probs hi-only
__device__ __half g_fused2[(size_t)NR * 4 * DC];        // fused split [8192,4096]

// ---------------------------------------------------------------------------
// helpers
// ---------------------------------------------------------------------------
__device__ __forceinline__ uint32_t smem_u32(const void* p) {
    uint32_t a;
    asm("{ .reg .u64 t; cvta.to.shared.u64 t, %1; cvt.u32.u64 %0, t; }" : "=r"(a) : "l"(p));
    return a;
}
__device__ __forceinline__ void cp16(uint32_t d, const void* g) {
    asm volatile("cp.async.cg.shared.global [%0], [%1], 16;"
                 :: "r"(d), "l"(__cvta_generic_to_global(g)) : "memory");
}
__device__ __forceinline__ void ldm4(uint32_t* r, uint32_t a) {
    asm volatile("ldmatrix.sync.aligned.m8n8.x4.shared.b16 {%0,%1,%2,%3}, [%4];"
                 : "=r"(r[0]), "=r"(r[1]), "=r"(r[2]), "=r"(r[3]) : "r"(a));
}
__device__ __forceinline__ void mma16816(float* d, const uint32_t* a, const uint32_t* b) {
    asm("mma.sync.aligned.m16n8k16.row.col.f32.f16.f16.f32 "
        "{%0,%1,%2,%3}, {%4,%5,%6,%7}, {%8,%9}, {%0,%1,%2,%3};"
        : "+f"(d[0]), "+f"(d[1]), "+f"(d[2]), "+f"(d[3])
        : "r"(a[0]), "r"(a[1]), "r"(a[2]), "r"(a[3]), "r"(b[0]), "r"(b[1]));
}
__device__ __forceinline__ __half2 split_hi(float x0, float x1, __half2& lo) {
    __half h0 = __float2half_rn(x0), h1 = __float2half_rn(x1);
    lo = __halves2half2(__float2half_rn(x0 - __half2float(h0)),
                        __float2half_rn(x1 - __half2float(h1)));
    return __halves2half2(h0, h1);
}

// ---------------------------------------------------------------------------
// Split-fp16 NT GEMM:  C[M,N] = A[M,K] . B[N,K]^T
// PASSES=3: (Ahi,Bhi)+(Ahi,Blo)+(Alo,Bhi).  PASSES=1: (Ahi,Bhi) only.
// Tile 128x128xBK64, 256 threads, cp.async 3-stage, ldmatrix fragment loads.
// OUT_MODE: 0 = fp32 to Cf, 1 = split fp16 to Ch (hi at col, lo at col+lo_off)
// BIAS: 0 none, 1 per-column, 2 per-row
// ---------------------------------------------------------------------------
#define TPB 256
#define AST 144                       // 128B data + 16B pad (36 banks/row)
#define STG (128 * AST * 2)           // 36864 B per stage (A+B)
#define GSMEM (3 * STG)               // 110592 B

template <int OUT_MODE, int BIAS, int PASSES>
__global__ __launch_bounds__(TPB)
void hgemm3(const __half* __restrict__ A, const __half* __restrict__ B, int K,
            size_t ldA, size_t ldB,
            float* __restrict__ Cf, __half* __restrict__ Ch,
            int ldc, int lo_off, const float* __restrict__ bias)
{
    extern __shared__ char smc[];
    const uint32_t sb = smem_u32(smc);
    const int tid = threadIdx.x;
    const int wid = tid >> 5, lane = tid & 31;
    const int g = lane >> 2, t = lane & 3;
    const int wm = wid & 1, wn = wid >> 1;
    const int m0 = blockIdx.y * 128, n0 = blockIdx.x * 128;

    const int K64 = K >> 6;
    const int total = PASSES * K64;

    const int lr = tid >> 3;              // 0..31 (row base, step 32)
    const int lc  = (tid & 7) * 8;        // half offset within 64-col row
    const int lcB = (tid & 7) * 16;       // byte offset

    auto load_stage = [&](int s, int step) {
        if (step < total) {
            const int seg = step / K64, kk = step - seg * K64;
            const size_t ak = (size_t)((PASSES == 3 && seg == 2) ? K : 0) + (size_t)kk * 64;
            const size_t bk = (size_t)((PASSES >= 2 && seg == 1) ? K : 0) + (size_t)kk * 64;
            const __half* ga = A + (size_t)(m0 + lr) * ldA + ak + lc;
            const __half* gb = B + (size_t)(n0 + lr) * ldB + bk + lc;
            const uint32_t da = sb + s * STG + lr * AST + lcB;
            const uint32_t db = da + 128 * AST;
#pragma unroll
            for (int i = 0; i < 4; ++i) {
                cp16(da + i * 32 * AST, ga + (size_t)i * 32 * ldA);
                cp16(db + i * 32 * AST, gb + (size_t)i * 32 * ldB);
            }
        }
        asm volatile("cp.async.commit_group;" ::: "memory");
    };

    float acc[4][4][4];
#pragma unroll
    for (int i = 0; i < 4; ++i)
#pragma unroll
        for (int j = 0; j < 4; ++j)
#pragma unroll
            for (int r = 0; r < 4; ++r) acc[i][j][r] = 0.0f;

    // ldmatrix per-lane offsets within a stage
    const uint32_t aoff = (uint32_t)(wm * 64 + (lane & 15)) * AST + ((lane >> 4) << 4);
    const uint32_t boff = 128 * AST +
        (uint32_t)(wn * 32 + ((lane & 7) | ((lane >> 1) & 8))) * AST +
        (((lane >> 3) & 1) << 4);

    load_stage(0, 0);
    load_stage(1, 1);

    for (int step = 0; step < total; ++step) {
        asm volatile("cp.async.wait_group 1;" ::: "memory");
        __syncthreads();
        load_stage((step + 2) % 3, step + 2);

        const uint32_t sbase = sb + (step % 3) * STG;

#pragma unroll
        for (int kh = 0; kh < 4; ++kh) {            // four k16 pieces of BK=64
            const uint32_t ko = kh * 32;            // bytes
            uint32_t af[4][4], bf[4][2];
#pragma unroll
            for (int mt = 0; mt < 4; ++mt)
                ldm4(af[mt], sbase + aoff + (uint32_t)mt * 16 * AST + ko);
#pragma unroll
            for (int np = 0; np < 2; ++np) {
                uint32_t r[4];
                ldm4(r, sbase + boff + (uint32_t)np * 16 * AST + ko);
                bf[np * 2][0] = r[0];      bf[np * 2][1] = r[1];
                bf[np * 2 + 1][0] = r[2];  bf[np * 2 + 1][1] = r[3];
            }
#pragma unroll
            for (int mt = 0; mt < 4; ++mt)
#pragma unroll
                for (int nt = 0; nt < 4; ++nt)
                    mma16816(acc[mt][nt], af[mt], bf[nt]);
        }
    }

    // ---- epilogue ----
#pragma unroll
    for (int mt = 0; mt < 4; ++mt) {
        const int r0 = m0 + wm * 64 + mt * 16 + g;
        const int r1 = r0 + 8;
#pragma unroll
        for (int nt = 0; nt < 4; ++nt) {
            const int col = n0 + wn * 32 + nt * 8 + 2 * t;
            float v00 = acc[mt][nt][0], v01 = acc[mt][nt][1];
            float v10 = acc[mt][nt][2], v11 = acc[mt][nt][3];
            if (BIAS == 1) {
                const float b0 = bias[col], b1 = bias[col + 1];
                v00 += b0; v01 += b1; v10 += b0; v11 += b1;
            } else if (BIAS == 2) {
                const float b0 = bias[r0], b1 = bias[r1];
                v00 += b0; v01 += b0; v10 += b1; v11 += b1;
            }
            if (OUT_MODE == 0) {
                *reinterpret_cast<float2*>(&Cf[(size_t)r0 * ldc + col]) = make_float2(v00, v01);
                *reinterpret_cast<float2*>(&Cf[(size_t)r1 * ldc + col]) = make_float2(v10, v11);
            } else {
                __half2 lo0, lo1;
                __half2 hi0 = split_hi(v00, v01, lo0);
                __half2 hi1 = split_hi(v10, v11, lo1);
                __half2* p0 = reinterpret_cast<__half2*>(&Ch[(size_t)r0 * ldc + col]);
                __half2* p1 = reinterpret_cast<__half2*>(&Ch[(size_t)r1 * ldc + col]);
                p0[0] = hi0;  p0[lo_off / 2] = lo0;
                p1[0] = hi1;  p1[lo_off / 2] = lo1;
            }
        }
    }
}

// ---------------------------------------------------------------------------
// fp32 [R,C] -> split fp16 [R,2C]
// ---------------------------------------------------------------------------
__global__ __launch_bounds__(256)
void convert_split(const float* __restrict__ in, __half* __restrict__ out,
                   int C, size_t total)
{
    size_t i = ((size_t)blockIdx.x * 256 + threadIdx.x) * 4;
    if (i >= total) return;
    float4 v = *reinterpret_cast<const float4*>(&in[i]);
    size_t r = i / C;
    int c = (int)(i - r * C);
    __half2 lo0, lo1;
    __half2 hi0 = split_hi(v.x, v.y, lo0);
    __half2 hi1 = split_hi(v.z, v.w, lo1);
    __half* row = out + r * (2 * (size_t)C);
    *reinterpret_cast<__half2*>(&row[c])         = hi0;
    *reinterpret_cast<__half2*>(&row[c + 2])     = hi1;
    *reinterpret_cast<__half2*>(&row[C + c])     = lo0;
    *reinterpret_cast<__half2*>(&row[C + c + 2]) = lo1;
}

// ---------------------------------------------------------------------------
// All 7 weight transposes in ONE launch: in[R,C] -> split fp16 out[C,2R].
// blockIdx.z selects the tensor; grid is sized for the largest (Wo).
// ---------------------------------------------------------------------------
__global__ __launch_bounds__(256)
void weight_prep(const float* w0, const float* w1, const float* w2c,
                 const float* w3, const float* w4, const float* w5,
                 const float* w6,
                 __half* o0, __half* o1, __half* o2, __half* o3,
                 __half* o4, __half* o5, __half* o6)
{
    const float* src; __half* dst; int R, C;
    switch (blockIdx.z) {
        case 0: src = w0; dst = o0; R = DC; C = DC; break;
        case 1: src = w1; dst = o1; R = DC; C = DC; break;
        case 2: src = w2c; dst = o2; R = DC; C = DC; break;
        case 3: src = w3; dst = o3; R = DC; C = DC; break;
        case 4: src = w4; dst = o4; R = DC; C = DC; break;
        case 5: src = w5; dst = o5; R = DC; C = DC; break;
        default: src = w6; dst = o6; R = 2 * DC; C = 2 * DC; break;
    }
    const int bx = blockIdx.x * 32, by = blockIdx.y * 32;
    if (bx >= C || by >= R) return;

    __shared__ float tl[32][33];
    const int tx = threadIdx.x, ty = threadIdx.y;
#pragma unroll
    for (int j = ty; j < 32; j += 8)
        tl[j][tx] = src[(size_t)(by + j) * C + bx + tx];
    __syncthreads();
#pragma unroll
    for (int j = ty; j < 32; j += 8) {
        const float v = tl[tx][j];
        const __half h = __float2half_rn(v);
        const __half l = __float2half_rn(v - __half2float(h));
        __half* row = dst + (size_t)(bx + j) * (2 * (size_t)R);
        row[by + tx]     = h;
        row[R + by + tx] = l;
    }
}

// ---------------------------------------------------------------------------
// Row softmax: fp32 logits -> fp16 probs (hi only, compact [NR,NR])
// ---------------------------------------------------------------------------
__global__ __launch_bounds__(256)
void softmax_hi(const float* __restrict__ S, __half* __restrict__ S2)
{
    __shared__ float row[NR];
    __shared__ float red[256];
    const float* p = S + (size_t)blockIdx.x * NR;
    __half* o = S2 + (size_t)blockIdx.x * NR;
    const int tid = threadIdx.x;

    float lmax = -3.0e38f;
    for (int i = tid * 4; i < NR; i += 1024) {
        float4 v = *reinterpret_cast<const float4*>(&p[i]);
        *reinterpret_cast<float4*>(&row[i]) = v;
        lmax = fmaxf(lmax, fmaxf(fmaxf(v.x, v.y), fmaxf(v.z, v.w)));
    }
    red[tid] = lmax;
    __syncthreads();
#pragma unroll
    for (int s = 128; s > 0; s >>= 1) {
        if (tid < s) red[tid] = fmaxf(red[tid], red[tid + s]);
        __syncthreads();
    }
    const float bmax = red[0];
    __syncthreads();

    float lsum = 0.0f;
    for (int i = tid * 4; i < NR; i += 1024) {
        float4 v = *reinterpret_cast<float4*>(&row[i]);
        v.x = __expf(v.x - bmax); v.y = __expf(v.y - bmax);
        v.z = __expf(v.z - bmax); v.w = __expf(v.w - bmax);
        lsum += v.x + v.y + v.z + v.w;
        *reinterpret_cast<float4*>(&row[i]) = v;
    }
    red[tid] = lsum;
    __syncthreads();
#pragma unroll
    for (int s = 128; s > 0; s >>= 1) {
        if (tid < s) red[tid] += red[tid + s];
        __syncthreads();
    }
    const float inv = 1.0f / red[0];
    __syncthreads();

    for (int i = tid * 4; i < NR; i += 1024) {
        float4 v = *reinterpret_cast<float4*>(&row[i]);
        *reinterpret_cast<__half2*>(&o[i]) =
            __halves2half2(__float2half_rn(v.x * inv), __float2half_rn(v.y * inv));
        *reinterpret_cast<__half2*>(&o[i + 2]) =
            __halves2half2(__float2half_rn(v.z * inv), __float2half_rn(v.w * inv));
    }
}

// ---------------------------------------------------------------------------
// Launch sequence
// ---------------------------------------------------------------------------
extern "C" void kernel_launch(void* const* d_in, const int* in_sizes, int n_in,
                              void* d_out, int out_size)
{
    const float* img = (const float*)d_in[0];
    const float* tab = (const float*)d_in[1];
    const float* Wqi = (const float*)d_in[2];  const float* bqi = (const float*)d_in[3];
    const float* Wkt = (const float*)d_in[4];  const float* bkt = (const float*)d_in[5];
    const float* Wvt = (const float*)d_in[6];  const float* bvt = (const float*)d_in[7];
    const float* Wqt = (const float*)d_in[8];  const float* bqt = (const float*)d_in[9];
    const float* Wki = (const float*)d_in[10]; const float* bki = (const float*)d_in[11];
    const float* Wvi = (const float*)d_in[12]; const float* bvi = (const float*)d_in[13];
    const float* Wo  = (const float*)d_in[14]; const float* bo  = (const float*)d_in[15];
    float* out = (float*)d_out;

    cudaFuncSetAttribute(hgemm3<0,0,3>, cudaFuncAttributeMaxDynamicSharedMemorySize, GSMEM);
    cudaFuncSetAttribute(hgemm3<0,1,3>, cudaFuncAttributeMaxDynamicSharedMemorySize, GSMEM);
    cudaFuncSetAttribute(hgemm3<1,0,1>, cudaFuncAttributeMaxDynamicSharedMemorySize, GSMEM);
    cudaFuncSetAttribute(hgemm3<1,1,3>, cudaFuncAttributeMaxDynamicSharedMemorySize, GSMEM);
    cudaFuncSetAttribute(hgemm3<1,2,3>, cudaFuncAttributeMaxDynamicSharedMemorySize, GSMEM);

    float *S;
    __half *img2, *tab2, *w2, *wo2, *qk2, *vt2, *S2, *fused2;
    cudaGetSymbolAddress((void**)&S,      g_S);
    cudaGetSymbolAddress((void**)&img2,   g_img2);
    cudaGetSymbolAddress((void**)&tab2,   g_tab2);
    cudaGetSymbolAddress((void**)&w2,     g_w2);
    cudaGetSymbolAddress((void**)&wo2,    g_wo2);
    cudaGetSymbolAddress((void**)&qk2,    g_qk2);
    cudaGetSymbolAddress((void**)&vt2,    g_vt2);
    cudaGetSymbolAddress((void**)&S2,     g_S2);
    cudaGetSymbolAddress((void**)&fused2, g_fused2);

    const size_t W2SZ = (size_t)DC * 2 * DC;
    __half* wqi2 = w2 + 0 * W2SZ;  __half* wkt2 = w2 + 1 * W2SZ;
    __half* wvt2 = w2 + 2 * W2SZ;  __half* wqt2 = w2 + 3 * W2SZ;
    __half* wki2 = w2 + 4 * W2SZ;  __half* wvi2 = w2 + 5 * W2SZ;
    const size_t QK2 = (size_t)NR * 2 * DC;
    __half* q12 = qk2 + 0 * QK2;   __half* k12 = qk2 + 1 * QK2;
    __half* q22 = qk2 + 2 * QK2;   __half* k22 = qk2 + 3 * QK2;
    __half* v1t2 = vt2;            __half* v2t2 = vt2 + (size_t)DC * 2 * NR;

    // ---- launches 0-2: input conversions + combined weight prep ----
    const size_t tot = (size_t)NR * DC;
    convert_split<<<(unsigned)((tot / 4 + 255) / 256), 256>>>(img, img2, DC, tot);
    convert_split<<<(unsigned)((tot / 4 + 255) / 256), 256>>>(tab, tab2, DC, tot);
    weight_prep<<<dim3(64, 64, 7), dim3(32, 8)>>>(
        Wqi, Wkt, Wvt, Wqt, Wki, Wvi, Wo,
        wqi2, wkt2, wvt2, wqt2, wki2, wvi2, wo2);

    // ---- launches 3-8: projections (3-pass) — ncu -s 5 catches one of these
    dim3 gP(DC / 128, NR / 128);
    hgemm3<1,1,3><<<gP, TPB, GSMEM>>>(img2, wqi2, DC, 2*DC, 2*DC, nullptr, q12, 2*DC, DC, bqi);
    hgemm3<1,1,3><<<gP, TPB, GSMEM>>>(tab2, wkt2, DC, 2*DC, 2*DC, nullptr, k12, 2*DC, DC, bkt);
    hgemm3<1,1,3><<<gP, TPB, GSMEM>>>(tab2, wqt2, DC, 2*DC, 2*DC, nullptr, q22, 2*DC, DC, bqt);
    hgemm3<1,1,3><<<gP, TPB, GSMEM>>>(img2, wki2, DC, 2*DC, 2*DC, nullptr, k22, 2*DC, DC, bki);
    dim3 gV(NR / 128, DC / 128);
    hgemm3<1,2,3><<<gV, TPB, GSMEM>>>(wvt2, tab2, DC, 2*DC, 2*DC, nullptr, v1t2, 2*NR, NR, bvt);
    hgemm3<1,2,3><<<gV, TPB, GSMEM>>>(wvi2, img2, DC, 2*DC, 2*DC, nullptr, v2t2, 2*NR, NR, bvi);

    dim3 gS(NR / 128, NR / 128);
    dim3 gPV(DC / 128, NR / 128);

    // ---- branch 1: attended_tabular -> fused cols [1024,2048) ----
    hgemm3<0,0,3><<<gS, TPB, GSMEM>>>(q12, k12, DC, 2*DC, 2*DC, S, nullptr, NR, 0, nullptr);
    softmax_hi<<<NR, 256>>>(S, S2);
    hgemm3<1,0,1><<<gPV, TPB, GSMEM>>>(S2, v1t2, NR, NR, 2*NR, nullptr, fused2 + DC, 4*DC, 2*DC, nullptr);

    // ---- branch 2: attended_image -> fused cols [0,1024) ----
    hgemm3<0,0,3><<<gS, TPB, GSMEM>>>(q22, k22, DC, 2*DC, 2*DC, S, nullptr, NR, 0, nullptr);
    softmax_hi<<<NR, 256>>>(S, S2);
    hgemm3<1,0,1><<<gPV, TPB, GSMEM>>>(S2, v2t2, NR, NR, 2*NR, nullptr, fused2, 4*DC, 2*DC, nullptr);

    // ---- output projection (fp32 out, 3-pass) ----
    dim3 gO(2 * DC / 128, NR / 128);
    hgemm3<0,1,3><<<gO, TPB, GSMEM>>>(fused2, wo2, 2*DC, 4*DC, 4*DC, out, nullptr, 2*DC, 0, bo);
}